// round 13
// baseline (speedup 1.0000x reference)
#include <cuda_runtime.h>
#include <math.h>

// Problem constants
#define BSZ 32
#define SSZ 1024
#define DSZ 1024

typedef unsigned long long ull;

// Scratch buffers (device globals — no allocation allowed in kernel_launch).
// buf0: Z0 (= x@W0) -> overwritten in place with h0 (time-major [S,B,D])
// buf1: Z1 (= h0@W1) (time-major [S,B,D])
__device__ float g_buf0[(size_t)BSZ * SSZ * DSZ];
__device__ float g_buf1[(size_t)BSZ * SSZ * DSZ];
// Paired h state, double-buffered by parity: g_hp[p][b][j] = (h[b][j], h[b][j+512])
__device__ float2 g_hp[2][BSZ][DSZ / 2];

// Central grid-barrier state (zero-initialized; restored at launch end).
__device__ unsigned g_bar_count;
__device__ unsigned g_bar_flag;

// ---------------------------------------------------------------------------
// Packed f32x2 helpers (sm_100+). Each lane is an independent IEEE fp32 FMA —
// bit-identical to two scalar fmaf chains.
// ---------------------------------------------------------------------------
__device__ __forceinline__ ull fma2(ull a, ull b, ull c) {
    ull d;
    asm("fma.rn.f32x2 %0, %1, %2, %3;" : "=l"(d) : "l"(a), "l"(b), "l"(c));
    return d;
}
__device__ __forceinline__ void unpack2(ull v, float& lo, float& hi) {
    asm("mov.b64 {%0, %1}, %2;" : "=f"(lo), "=f"(hi) : "l"(v));
}
__device__ __forceinline__ ull pack2(float lo, float hi) {
    ull r;
    asm("mov.b64 %0, {%1, %2};" : "=l"(r) : "f"(lo), "f"(hi));
    return r;
}

// ---------------------------------------------------------------------------
// Reference arithmetic (validated bit-exact in rounds 9-11):
//   dot  = split-K=2: two ascending fp32 fmaf chains of 512, combined s0+s1
//   z    = (x@W + h@U) + b  (rn adds, that order)
//   tanh = XLA fast-tanh with_fma: clamp +-7.99881172180175781, FMA Horner,
//          rn divide, |x|<0.0004 passthrough.
// ---------------------------------------------------------------------------
__device__ __forceinline__ float xla_tanh(float x) {
    const float kMax = 7.99881172180175781f;
    float ax = fabsf(x);
    float xc = fminf(fmaxf(x, -kMax), kMax);
    float x2 = __fmul_rn(xc, xc);
    float p = -2.76076847742355e-16f;
    p = fmaf(x2, p, 2.00018790482477e-13f);
    p = fmaf(x2, p, -8.60467152213735e-11f);
    p = fmaf(x2, p, 5.12229709037114e-08f);
    p = fmaf(x2, p, 1.48572235717979e-05f);
    p = fmaf(x2, p, 6.37261928875436e-04f);
    p = fmaf(x2, p, 4.89352455891786e-03f);
    p = __fmul_rn(xc, p);
    float q = 1.19825839466702e-06f;
    q = fmaf(x2, q, 1.18534705686654e-04f);
    q = fmaf(x2, q, 2.26843463243900e-03f);
    q = fmaf(x2, q, 4.89352518554385e-03f);
    float r = __fdiv_rn(p, q);
    return (ax < 0.0004f) ? x : r;
}

// ---------------------------------------------------------------------------
// FFMA2 GEMM: C = A @ W (no bias). The two split-K chains (k<512, k>=512) are
// independent -> packed into f32x2 lanes; pairs built at SMEM-store time.
// Lane0 accumulates k=0..511 ascending, lane1 k=512..1023; final lo+hi (rn).
//   remap=1: A row m = b*S + s  ->  C row = s*B + b   (x -> time-major Z0)
//   remap=0: C row = m
// ---------------------------------------------------------------------------
__global__ __launch_bounds__(256) void gemm_kernel(
    const float* __restrict__ A_ext, int a_sel,
    const float* __restrict__ W,
    int c_sel, int remap)
{
    const int N_ = DSZ, K_ = DSZ;
    const float* A = (a_sel == 0) ? (const float*)g_buf0 : A_ext;
    float* C = (c_sel == 0) ? g_buf0 : g_buf1;

    __shared__ ull As2[8][132];   // [klo][m] pairs, padded row
    __shared__ ull Bs2[8][66];    // [klo][n] pairs, padded row

    const int tid = threadIdx.x;
    const int tx = tid & 15;
    const int ty = tid >> 4;
    const int m0 = blockIdx.y * 128;
    const int n0 = blockIdx.x * 64;

    ull acc2[8][4];
#pragma unroll
    for (int i = 0; i < 8; i++)
#pragma unroll
        for (int j = 0; j < 4; j++) acc2[i][j] = 0ull;

    const int arow = tid >> 1;
    const int akq = (tid & 1) * 4;
    const int brow = tid >> 4;
    const int bnq = (tid & 15) * 4;

    for (int kt = 0; kt < 512; kt += 8) {
        {
            float4 lo = *(const float4*)&A[(size_t)(m0 + arow) * K_ + kt + akq];
            float4 hi = *(const float4*)&A[(size_t)(m0 + arow) * K_ + kt + 512 + akq];
            As2[akq + 0][arow] = pack2(lo.x, hi.x);
            As2[akq + 1][arow] = pack2(lo.y, hi.y);
            As2[akq + 2][arow] = pack2(lo.z, hi.z);
            As2[akq + 3][arow] = pack2(lo.w, hi.w);
        }
        if (tid < 128) {
            float4 blo = *(const float4*)&W[(size_t)(kt + brow) * N_ + n0 + bnq];
            float4 bhi = *(const float4*)&W[(size_t)(kt + 512 + brow) * N_ + n0 + bnq];
            Bs2[brow][bnq + 0] = pack2(blo.x, bhi.x);
            Bs2[brow][bnq + 1] = pack2(blo.y, bhi.y);
            Bs2[brow][bnq + 2] = pack2(blo.z, bhi.z);
            Bs2[brow][bnq + 3] = pack2(blo.w, bhi.w);
        }
        __syncthreads();

#pragma unroll
        for (int kk = 0; kk < 8; kk++) {
            ull a2[8], b2[4];
#pragma unroll
            for (int i = 0; i < 8; i++) a2[i] = As2[kk][ty * 8 + i];
#pragma unroll
            for (int j = 0; j < 4; j++) b2[j] = Bs2[kk][tx * 4 + j];
#pragma unroll
            for (int i = 0; i < 8; i++)
#pragma unroll
                for (int j = 0; j < 4; j++)
                    acc2[i][j] = fma2(a2[i], b2[j], acc2[i][j]);
        }
        __syncthreads();
    }

#pragma unroll
    for (int i = 0; i < 8; i++) {
        int m = m0 + ty * 8 + i;
        int orow = remap ? ((m & (SSZ - 1)) * BSZ + (m >> 10)) : m;
        float lo, hi;
        float4 v;
        unpack2(acc2[i][0], lo, hi); v.x = __fadd_rn(lo, hi);
        unpack2(acc2[i][1], lo, hi); v.y = __fadd_rn(lo, hi);
        unpack2(acc2[i][2], lo, hi); v.z = __fadd_rn(lo, hi);
        unpack2(acc2[i][3], lo, hi); v.w = __fadd_rn(lo, hi);
        *(float4*)&C[(size_t)orow * N_ + n0 + tx * 4] = v;
    }
}

// ---------------------------------------------------------------------------
// Persistent recurrent kernel with SMEM staging + software-pipelined dot.
// Grid = 128 CTAs = 4 b-groups x 32 c-groups. CTA covers b in [b0,b0+8),
// c in [c0,c0+32); 256 threads, warp = 4 b-lanes x 8 c-lanes.
// Per step: cooperative bulk load of the CTA's 8 paired h rows (32KB,
// coalesced, MLP=8) into SMEM; dot reads h + U from SMEM through a 4-deep
// rotating register prefetch buffer (8 LDS.128 in flight) so the 29-cyc LDS
// latency never gates the dependent FFMA2 chain.
// Dynamic SMEM: Usp 32x514 float2 (131.6KB) + Hs 8x514 float2 (32.9KB).
// Central grid barrier (validated, monotonic release values).
// ---------------------------------------------------------------------------
#define USP_STRIDE 514
#define HS_STRIDE 514

__global__ __launch_bounds__(256, 1) void rnn_kernel(
    int z_sel, const float* __restrict__ U, const float* __restrict__ bias,
    float* H_ext, int h_is_ext, long hStrideT, long hStrideB)
{
    extern __shared__ __align__(16) float2 smem[];
    float2* Usp = smem;                      // [32][USP_STRIDE]
    float2* Hs = smem + 32 * USP_STRIDE;     // [8][HS_STRIDE]

    const float* Z = z_sel ? (const float*)g_buf1 : (const float*)g_buf0;
    float* H = h_is_ext ? H_ext : g_buf0;

    const int tid = threadIdx.x;
    const int bid = blockIdx.x;
    const int b0 = (bid >> 5) * 8;           // 4 b-groups of 8
    const int c0 = (bid & 31) * 32;          // 32 c-groups of 32

    // Stage paired U slice: Usp[c][j] = (U[j*D + c0+c], U[(j+512)*D + c0+c])
    for (int i = tid; i < 32 * 512; i += 256) {
        int c = i & 31;
        int j = i >> 5;
        float2 pr;
        pr.x = U[(size_t)j * DSZ + c0 + c];
        pr.y = U[(size_t)(j + 512) * DSZ + c0 + c];
        Usp[c * USP_STRIDE + j] = pr;
    }
    __syncthreads();

    const int w = tid >> 5;
    const int lane = tid & 31;
    const int b_l = (w >> 2) * 4 + (lane >> 3);   // 0..7
    const int c_l = (w & 3) * 8 + (lane & 7);     // 0..31
    const int b = b0 + b_l;
    const int cg = c0 + c_l;                      // global column

    const float bval = bias[cg];
    const unsigned nblocks = gridDim.x;
    // paired global store position for this thread's output
    const int jj = cg & 511;
    float* hp_store_base0 = (float*)&g_hp[0][b][jj] + ((cg < 512) ? 0 : 1);
    float* hp_store_base1 = (float*)&g_hp[1][b][jj] + ((cg < 512) ? 0 : 1);

    const ulonglong2* hrow = (const ulonglong2*)&Hs[b_l * HS_STRIDE];
    const ulonglong2* urow = (const ulonglong2*)&Usp[c_l * USP_STRIDE];

    for (int t = 0; t < SSZ; ++t) {
        if (t > 0) {
            // Bulk load CTA's 8 paired h rows (32KB contiguous) into SMEM.
            const ulonglong2* src =
                (const ulonglong2*)&g_hp[(t - 1) & 1][b0][0];
#pragma unroll
            for (int s = 0; s < 8; s++) {
                int g = tid + s * 256;            // 0..2047
                int r = g >> 8;
                int q2 = g & 255;
                ulonglong2 v = __ldcg(src + g);
                *(ulonglong2*)&Hs[r * HS_STRIDE + q2 * 2] = v;
            }
            __syncthreads();
        }

        float zW = __ldcg(&Z[((size_t)t * BSZ + b) * DSZ + cg]);
        float s_tot = 0.f;
        if (t > 0) {
            // 4-deep software pipeline: 8 LDS.128 in flight, consume slot q&3
            // while prefetching q+4. Chain order is untouched (bit-exact).
            ull s01 = 0;
            ulonglong2 hb[4], ub[4];
#pragma unroll
            for (int p = 0; p < 4; p++) { hb[p] = hrow[p]; ub[p] = urow[p]; }
#pragma unroll 8
            for (int q = 0; q < 256; q++) {
                const int slot = q & 3;
                ulonglong2 hv = hb[slot];
                ulonglong2 uv = ub[slot];
                if (q < 252) {
                    hb[slot] = hrow[q + 4];
                    ub[slot] = urow[q + 4];
                }
                s01 = fma2(hv.x, uv.x, s01);      // k = 2q   (both halves)
                s01 = fma2(hv.y, uv.y, s01);      // k = 2q+1 (both halves)
            }
            float s0, s1;
            unpack2(s01, s0, s1);
            s_tot = __fadd_rn(s0, s1);            // split-K combine p0 + p1
        }
        float z = __fadd_rn(__fadd_rn(zW, s_tot), bval);  // (dot1+dot2)+b
        float hv = xla_tanh(z);
        // normal layout (consumed by next GEMM / final output)
        H[(size_t)t * hStrideT + (size_t)b * hStrideB + cg] = hv;
        // paired layout for next step's bulk load
        *((t & 1) ? hp_store_base1 : hp_store_base0) = hv;

        if (t != SSZ - 1) {
            // Central grid barrier: release value = t+1 (monotonic in launch).
            __syncthreads();
            if (tid == 0) {
                __threadfence();
                unsigned prev = atomicAdd(&g_bar_count, 1u);
                if (prev == nblocks - 1u) {
                    atomicExch(&g_bar_count, 0u);   // reset BEFORE release
                    __threadfence();
                    atomicExch(&g_bar_flag, (unsigned)(t + 1));
                } else {
                    unsigned want = (unsigned)(t + 1);
                    unsigned f;
                    do {
                        asm volatile("ld.acquire.gpu.u32 %0, [%1];"
                                     : "=r"(f) : "l"(&g_bar_flag) : "memory");
                    } while (f < want);
                }
                __threadfence();
            }
            __syncthreads();
        }
    }

    // Cleanup: last-arriving CTA restores barrier state for graph replay.
    __syncthreads();
    if (tid == 0) {
        __threadfence();
        unsigned prev = atomicAdd(&g_bar_count, 1u);
        if (prev == nblocks - 1u) {
            atomicExch(&g_bar_count, 0u);
            __threadfence();
            atomicExch(&g_bar_flag, 0u);
        }
    }
}

// ---------------------------------------------------------------------------
// Launch: Z0 = x@W0  ->  scan layer0  ->  Z1 = h0@W1  ->  scan layer1
// ---------------------------------------------------------------------------
extern "C" void kernel_launch(void* const* d_in, const int* in_sizes, int n_in,
                              void* d_out, int out_size)
{
    const float* x  = (const float*)d_in[0];   // [B,S,D]
    const float* Wh = (const float*)d_in[1];   // [L,D,D]
    const float* Uh = (const float*)d_in[2];   // [L,D,D]
    const float* bb = (const float*)d_in[3];   // [L,D]
    float* out = (float*)d_out;                // [B,S,D]

    const int DD = DSZ * DSZ;
    dim3 ggrid(DSZ / 64, (BSZ * SSZ) / 128);   // (16, 256)

    const int smem_bytes = (32 * USP_STRIDE + 8 * HS_STRIDE) * sizeof(float2);
    cudaFuncSetAttribute(rnn_kernel,
                         cudaFuncAttributeMaxDynamicSharedMemorySize,
                         smem_bytes);

    // Layer 0: Z0 = x @ W0 (remap rows to time-major), into buf0
    gemm_kernel<<<ggrid, 256>>>(x, /*a_sel=*/-1, Wh, /*c_sel=*/0, /*remap=*/1);

    // Layer 0 scan: h0_t = tanh((Z0_t + h0_{t-1}@U0) + b0), in place in buf0
    rnn_kernel<<<128, 256, smem_bytes>>>(/*z_sel=*/0, Uh, bb, nullptr,
                                         /*h_is_ext=*/0,
                                         (long)(BSZ * DSZ), (long)DSZ);

    // Layer 1: Z1 = h0 @ W1 (rows already time-major), into buf1
    gemm_kernel<<<ggrid, 256>>>(nullptr, /*a_sel=*/0, Wh + DD,
                                /*c_sel=*/1, /*remap=*/0);

    // Layer 1 scan: out_t = tanh((Z1_t + out_{t-1}@U1) + b1), to d_out [B,S,D]
    rnn_kernel<<<128, 256, smem_bytes>>>(/*z_sel=*/1, Uh + DD, bb + DSZ, out,
                                         /*h_is_ext=*/1,
                                         (long)DSZ, (long)((size_t)SSZ * DSZ));
}

// round 14
// speedup vs baseline: 1.0103x; 1.0103x over previous
#include <cuda_runtime.h>
#include <math.h>

// Problem constants
#define BSZ 32
#define SSZ 1024
#define DSZ 1024

typedef unsigned long long ull;

// Scratch buffers (device globals — no allocation allowed in kernel_launch).
// buf0: Z0 (= x@W0) -> overwritten in place with h0 (time-major [S,B,D])
// buf1: Z1 (= h0@W1) (time-major [S,B,D])
__device__ float g_buf0[(size_t)BSZ * SSZ * DSZ];
__device__ float g_buf1[(size_t)BSZ * SSZ * DSZ];
// Paired h state, double-buffered by parity: g_hp[p][b][j] = (h[b][j], h[b][j+512])
__device__ float2 g_hp[2][BSZ][DSZ / 2];

// Per-b-group barrier state (4 groups x 32 CTAs). Each group's counter/flag
// lives in its own 128B line (stride 32 u32). Zero-init; restored at end.
__device__ unsigned g_bar_count[4 * 32];
__device__ unsigned g_bar_flag[4 * 32];

// ---------------------------------------------------------------------------
// Packed f32x2 helpers (sm_100+). Each lane is an independent IEEE fp32 FMA —
// bit-identical to two scalar fmaf chains.
// ---------------------------------------------------------------------------
__device__ __forceinline__ ull fma2(ull a, ull b, ull c) {
    ull d;
    asm("fma.rn.f32x2 %0, %1, %2, %3;" : "=l"(d) : "l"(a), "l"(b), "l"(c));
    return d;
}
__device__ __forceinline__ void unpack2(ull v, float& lo, float& hi) {
    asm("mov.b64 {%0, %1}, %2;" : "=f"(lo), "=f"(hi) : "l"(v));
}
__device__ __forceinline__ ull pack2(float lo, float hi) {
    ull r;
    asm("mov.b64 %0, {%1, %2};" : "=l"(r) : "f"(lo), "f"(hi));
    return r;
}

// ---------------------------------------------------------------------------
// Reference arithmetic (validated bit-exact in rounds 9-12):
//   dot  = split-K=2: two ascending fp32 fmaf chains of 512, combined s0+s1
//   z    = (x@W + h@U) + b  (rn adds, that order)
//   tanh = XLA fast-tanh with_fma: clamp +-7.99881172180175781, FMA Horner,
//          rn divide, |x|<0.0004 passthrough.
// ---------------------------------------------------------------------------
__device__ __forceinline__ float xla_tanh(float x) {
    const float kMax = 7.99881172180175781f;
    float ax = fabsf(x);
    float xc = fminf(fmaxf(x, -kMax), kMax);
    float x2 = __fmul_rn(xc, xc);
    float p = -2.76076847742355e-16f;
    p = fmaf(x2, p, 2.00018790482477e-13f);
    p = fmaf(x2, p, -8.60467152213735e-11f);
    p = fmaf(x2, p, 5.12229709037114e-08f);
    p = fmaf(x2, p, 1.48572235717979e-05f);
    p = fmaf(x2, p, 6.37261928875436e-04f);
    p = fmaf(x2, p, 4.89352455891786e-03f);
    p = __fmul_rn(xc, p);
    float q = 1.19825839466702e-06f;
    q = fmaf(x2, q, 1.18534705686654e-04f);
    q = fmaf(x2, q, 2.26843463243900e-03f);
    q = fmaf(x2, q, 4.89352518554385e-03f);
    float r = __fdiv_rn(p, q);
    return (ax < 0.0004f) ? x : r;
}

// ---------------------------------------------------------------------------
// FFMA2 GEMM: C = A @ W (no bias). The two split-K chains (k<512, k>=512) are
// independent -> packed into f32x2 lanes; pairs built at SMEM-store time.
// Lane0 accumulates k=0..511 ascending, lane1 k=512..1023; final lo+hi (rn).
//   remap=1: A row m = b*S + s  ->  C row = s*B + b   (x -> time-major Z0)
//   remap=0: C row = m
// ---------------------------------------------------------------------------
__global__ __launch_bounds__(256) void gemm_kernel(
    const float* __restrict__ A_ext, int a_sel,
    const float* __restrict__ W,
    int c_sel, int remap)
{
    const int N_ = DSZ, K_ = DSZ;
    const float* A = (a_sel == 0) ? (const float*)g_buf0 : A_ext;
    float* C = (c_sel == 0) ? g_buf0 : g_buf1;

    __shared__ ull As2[8][132];   // [klo][m] pairs, padded row
    __shared__ ull Bs2[8][66];    // [klo][n] pairs, padded row

    const int tid = threadIdx.x;
    const int tx = tid & 15;
    const int ty = tid >> 4;
    const int m0 = blockIdx.y * 128;
    const int n0 = blockIdx.x * 64;

    ull acc2[8][4];
#pragma unroll
    for (int i = 0; i < 8; i++)
#pragma unroll
        for (int j = 0; j < 4; j++) acc2[i][j] = 0ull;

    const int arow = tid >> 1;
    const int akq = (tid & 1) * 4;
    const int brow = tid >> 4;
    const int bnq = (tid & 15) * 4;

    for (int kt = 0; kt < 512; kt += 8) {
        {
            float4 lo = *(const float4*)&A[(size_t)(m0 + arow) * K_ + kt + akq];
            float4 hi = *(const float4*)&A[(size_t)(m0 + arow) * K_ + kt + 512 + akq];
            As2[akq + 0][arow] = pack2(lo.x, hi.x);
            As2[akq + 1][arow] = pack2(lo.y, hi.y);
            As2[akq + 2][arow] = pack2(lo.z, hi.z);
            As2[akq + 3][arow] = pack2(lo.w, hi.w);
        }
        if (tid < 128) {
            float4 blo = *(const float4*)&W[(size_t)(kt + brow) * N_ + n0 + bnq];
            float4 bhi = *(const float4*)&W[(size_t)(kt + 512 + brow) * N_ + n0 + bnq];
            Bs2[brow][bnq + 0] = pack2(blo.x, bhi.x);
            Bs2[brow][bnq + 1] = pack2(blo.y, bhi.y);
            Bs2[brow][bnq + 2] = pack2(blo.z, bhi.z);
            Bs2[brow][bnq + 3] = pack2(blo.w, bhi.w);
        }
        __syncthreads();

#pragma unroll
        for (int kk = 0; kk < 8; kk++) {
            ull a2[8], b2[4];
#pragma unroll
            for (int i = 0; i < 8; i++) a2[i] = As2[kk][ty * 8 + i];
#pragma unroll
            for (int j = 0; j < 4; j++) b2[j] = Bs2[kk][tx * 4 + j];
#pragma unroll
            for (int i = 0; i < 8; i++)
#pragma unroll
                for (int j = 0; j < 4; j++)
                    acc2[i][j] = fma2(a2[i], b2[j], acc2[i][j]);
        }
        __syncthreads();
    }

#pragma unroll
    for (int i = 0; i < 8; i++) {
        int m = m0 + ty * 8 + i;
        int orow = remap ? ((m & (SSZ - 1)) * BSZ + (m >> 10)) : m;
        float lo, hi;
        float4 v;
        unpack2(acc2[i][0], lo, hi); v.x = __fadd_rn(lo, hi);
        unpack2(acc2[i][1], lo, hi); v.y = __fadd_rn(lo, hi);
        unpack2(acc2[i][2], lo, hi); v.z = __fadd_rn(lo, hi);
        unpack2(acc2[i][3], lo, hi); v.w = __fadd_rn(lo, hi);
        *(float4*)&C[(size_t)orow * N_ + n0 + tx * 4] = v;
    }
}

// ---------------------------------------------------------------------------
// Persistent recurrent kernel with SMEM staging + software-pipelined dot
// + PER-B-GROUP barriers.
// Grid = 128 CTAs = 4 b-groups x 32 c-groups. CTA covers b in [b0,b0+8),
// c in [c0,c0+32); 256 threads, warp = 4 b-lanes x 8 c-lanes.
// KEY: the 4 b-groups are independent recurrence chains — CTA (g, c) only
// consumes h produced by the 32 CTAs of group g. So each step syncs only
// within the group: 32-way atomic chain (~0.9K cyc) instead of 128-way
// (~3.5K), with per-group flags in separate cache lines.
// Dynamic SMEM: Usp 32x514 float2 (131.6KB) + Hs 8x514 float2 (32.9KB).
// ---------------------------------------------------------------------------
#define USP_STRIDE 514
#define HS_STRIDE 514

__global__ __launch_bounds__(256, 1) void rnn_kernel(
    int z_sel, const float* __restrict__ U, const float* __restrict__ bias,
    float* H_ext, int h_is_ext, long hStrideT, long hStrideB)
{
    extern __shared__ __align__(16) float2 smem[];
    float2* Usp = smem;                      // [32][USP_STRIDE]
    float2* Hs = smem + 32 * USP_STRIDE;     // [8][HS_STRIDE]

    const float* Z = z_sel ? (const float*)g_buf1 : (const float*)g_buf0;
    float* H = h_is_ext ? H_ext : g_buf0;

    const int tid = threadIdx.x;
    const int bid = blockIdx.x;
    const int grp = bid >> 5;                // b-group 0..3
    const int b0 = grp * 8;                  // 8 b-rows per group
    const int c0 = (bid & 31) * 32;          // 32 c-groups of 32

    unsigned* bar_count = &g_bar_count[grp * 32];
    unsigned* bar_flag = &g_bar_flag[grp * 32];

    // Stage paired U slice: Usp[c][j] = (U[j*D + c0+c], U[(j+512)*D + c0+c])
    for (int i = tid; i < 32 * 512; i += 256) {
        int c = i & 31;
        int j = i >> 5;
        float2 pr;
        pr.x = U[(size_t)j * DSZ + c0 + c];
        pr.y = U[(size_t)(j + 512) * DSZ + c0 + c];
        Usp[c * USP_STRIDE + j] = pr;
    }
    __syncthreads();

    const int w = tid >> 5;
    const int lane = tid & 31;
    const int b_l = (w >> 2) * 4 + (lane >> 3);   // 0..7
    const int c_l = (w & 3) * 8 + (lane & 7);     // 0..31
    const int b = b0 + b_l;
    const int cg = c0 + c_l;                      // global column

    const float bval = bias[cg];
    // paired global store position for this thread's output
    const int jj = cg & 511;
    float* hp_store_base0 = (float*)&g_hp[0][b][jj] + ((cg < 512) ? 0 : 1);
    float* hp_store_base1 = (float*)&g_hp[1][b][jj] + ((cg < 512) ? 0 : 1);

    const ulonglong2* hrow = (const ulonglong2*)&Hs[b_l * HS_STRIDE];
    const ulonglong2* urow = (const ulonglong2*)&Usp[c_l * USP_STRIDE];

    for (int t = 0; t < SSZ; ++t) {
        if (t > 0) {
            // Bulk load group's 8 paired h rows (32KB contiguous) into SMEM.
            const ulonglong2* src =
                (const ulonglong2*)&g_hp[(t - 1) & 1][b0][0];
#pragma unroll
            for (int s = 0; s < 8; s++) {
                int g = tid + s * 256;            // 0..2047
                int r = g >> 8;
                int q2 = g & 255;
                ulonglong2 v = __ldcg(src + g);
                *(ulonglong2*)&Hs[r * HS_STRIDE + q2 * 2] = v;
            }
            __syncthreads();
        }

        float zW = __ldcg(&Z[((size_t)t * BSZ + b) * DSZ + cg]);
        float s_tot = 0.f;
        if (t > 0) {
            // 4-deep software pipeline: 8 LDS.128 in flight, consume slot q&3
            // while prefetching q+4. Chain order is untouched (bit-exact).
            ull s01 = 0;
            ulonglong2 hb[4], ub[4];
#pragma unroll
            for (int p = 0; p < 4; p++) { hb[p] = hrow[p]; ub[p] = urow[p]; }
#pragma unroll 8
            for (int q = 0; q < 256; q++) {
                const int slot = q & 3;
                ulonglong2 hv = hb[slot];
                ulonglong2 uv = ub[slot];
                if (q < 252) {
                    hb[slot] = hrow[q + 4];
                    ub[slot] = urow[q + 4];
                }
                s01 = fma2(hv.x, uv.x, s01);      // k = 2q   (both halves)
                s01 = fma2(hv.y, uv.y, s01);      // k = 2q+1 (both halves)
            }
            float s0, s1;
            unpack2(s01, s0, s1);
            s_tot = __fadd_rn(s0, s1);            // split-K combine p0 + p1
        }
        float z = __fadd_rn(__fadd_rn(zW, s_tot), bval);  // (dot1+dot2)+b
        float hv = xla_tanh(z);
        // normal layout (consumed by next GEMM / final output)
        H[(size_t)t * hStrideT + (size_t)b * hStrideB + cg] = hv;
        // paired layout for next step's bulk load
        *((t & 1) ? hp_store_base1 : hp_store_base0) = hv;

        if (t != SSZ - 1) {
            // Per-group barrier (32 CTAs): release value = t+1 (monotonic).
            __syncthreads();
            if (tid == 0) {
                __threadfence();
                unsigned prev = atomicAdd(bar_count, 1u);
                if (prev == 31u) {
                    atomicExch(bar_count, 0u);      // reset BEFORE release
                    __threadfence();
                    atomicExch(bar_flag, (unsigned)(t + 1));
                } else {
                    unsigned want = (unsigned)(t + 1);
                    unsigned f;
                    do {
                        asm volatile("ld.acquire.gpu.u32 %0, [%1];"
                                     : "=r"(f) : "l"(bar_flag) : "memory");
                    } while (f < want);
                }
                __threadfence();
            }
            __syncthreads();
        }
    }

    // Cleanup: last-arriving CTA of each group restores its barrier state.
    __syncthreads();
    if (tid == 0) {
        __threadfence();
        unsigned prev = atomicAdd(bar_count, 1u);
        if (prev == 31u) {
            atomicExch(bar_count, 0u);
            __threadfence();
            atomicExch(bar_flag, 0u);
        }
    }
}

// ---------------------------------------------------------------------------
// Launch: Z0 = x@W0  ->  scan layer0  ->  Z1 = h0@W1  ->  scan layer1
// ---------------------------------------------------------------------------
extern "C" void kernel_launch(void* const* d_in, const int* in_sizes, int n_in,
                              void* d_out, int out_size)
{
    const float* x  = (const float*)d_in[0];   // [B,S,D]
    const float* Wh = (const float*)d_in[1];   // [L,D,D]
    const float* Uh = (const float*)d_in[2];   // [L,D,D]
    const float* bb = (const float*)d_in[3];   // [L,D]
    float* out = (float*)d_out;                // [B,S,D]

    const int DD = DSZ * DSZ;
    dim3 ggrid(DSZ / 64, (BSZ * SSZ) / 128);   // (16, 256)

    const int smem_bytes = (32 * USP_STRIDE + 8 * HS_STRIDE) * sizeof(float2);
    cudaFuncSetAttribute(rnn_kernel,
                         cudaFuncAttributeMaxDynamicSharedMemorySize,
                         smem_bytes);

    // Layer 0: Z0 = x @ W0 (remap rows to time-major), into buf0
    gemm_kernel<<<ggrid, 256>>>(x, /*a_sel=*/-1, Wh, /*c_sel=*/0, /*remap=*/1);

    // Layer 0 scan: h0_t = tanh((Z0_t + h0_{t-1}@U0) + b0), in place in buf0
    rnn_kernel<<<128, 256, smem_bytes>>>(/*z_sel=*/0, Uh, bb, nullptr,
                                         /*h_is_ext=*/0,
                                         (long)(BSZ * DSZ), (long)DSZ);

    // Layer 1: Z1 = h0 @ W1 (rows already time-major), into buf1
    gemm_kernel<<<ggrid, 256>>>(nullptr, /*a_sel=*/0, Wh + DD,
                                /*c_sel=*/1, /*remap=*/0);

    // Layer 1 scan: out_t = tanh((Z1_t + out_{t-1}@U1) + b1), to d_out [B,S,D]
    rnn_kernel<<<128, 256, smem_bytes>>>(/*z_sel=*/1, Uh + DD, bb + DSZ, out,
                                         /*h_is_ext=*/1,
                                         (long)DSZ, (long)((size_t)SSZ * DSZ));
}